// round 1
// baseline (speedup 1.0000x reference)
#include <cuda_runtime.h>
#include <stdint.h>

#define NN 50000
#define NE 640000
#define D  128
#define TILE_M 64

// Scratch (no allocations allowed)
__device__ float g_h[NN * D];     // post-GEMM features
__device__ float g_agg[NN * D];   // aggregated features (layers 1,2)
__device__ float g_deg[NN];
__device__ float g_dis[NN];
__device__ int   g_is64;

// ---------------------------------------------------------------------------
// Detect whether edge_index is int64 or int32. Values are uniform in
// [0, 50000); int32 data reinterpreted as int64 combines two values into
// a + (b<<32) which is >= NN unless b==0 (prob ~2e-5 per element).
__global__ void detect_idx_kernel(const void* ei) {
    const long long* p = (const long long*)ei;
    int ok = 1;
    #pragma unroll
    for (int i = 0; i < 8; i++) {
        long long v = p[i];
        if (v < 0 || v >= NN) ok = 0;
    }
    g_is64 = ok;
}

__device__ __forceinline__ int edge_at(const void* ei, int pos) {
    if (g_is64) return (int)((const long long*)ei)[pos];
    return ((const int*)ei)[pos];
}

// ---------------------------------------------------------------------------
__global__ void deg_init_kernel() {
    int i = blockIdx.x * blockDim.x + threadIdx.x;
    if (i < NN) g_deg[i] = 1.0f;  // self-loop
}

__global__ void deg_count_kernel(const void* ei) {
    int e = blockIdx.x * blockDim.x + threadIdx.x;
    if (e >= NE) return;
    int col = edge_at(ei, NE + e);
    atomicAdd(&g_deg[col], 1.0f);
}

__global__ void dis_fin_kernel() {
    int i = blockIdx.x * blockDim.x + threadIdx.x;
    if (i < NN) g_dis[i] = rsqrtf(g_deg[i]);
}

// ---------------------------------------------------------------------------
// C[n x 128] = A[n x 128] @ W[128 x 128], optional ReLU on A read.
// Block: 256 threads, 64-row tile, full K staged in smem (96 KB dynamic).
__global__ void gemm_kernel(const float* __restrict__ Ain,
                            const float* __restrict__ W,
                            int n, int relu_in, int src_is_agg) {
    extern __shared__ float sm[];
    float* As = sm;               // 64 * 128
    float* Ws = sm + TILE_M * D;  // 128 * 128

    const float* A = src_is_agg ? g_agg : Ain;
    int tid  = threadIdx.x;
    int row0 = blockIdx.x * TILE_M;

    // Load W (16384 floats = 4096 float4)
    const float4* W4  = (const float4*)W;
    float4*       Ws4 = (float4*)Ws;
    #pragma unroll
    for (int i = 0; i < 16; i++) Ws4[tid + i * 256] = W4[tid + i * 256];

    // Load A tile (64 x 128 = 2048 float4), zero-pad tail rows
    const float4* A4  = (const float4*)A;
    float4*       As4 = (float4*)As;
    #pragma unroll
    for (int i = 0; i < 8; i++) {
        int idx = tid + i * 256;
        int r   = idx >> 5;           // idx / 32
        int c4  = idx & 31;
        float4 v = make_float4(0.f, 0.f, 0.f, 0.f);
        if (row0 + r < n) {
            v = A4[(size_t)(row0 + r) * 32 + c4];
            if (relu_in) {
                v.x = fmaxf(v.x, 0.f); v.y = fmaxf(v.y, 0.f);
                v.z = fmaxf(v.z, 0.f); v.w = fmaxf(v.w, 0.f);
            }
        }
        As4[idx] = v;
    }
    __syncthreads();

    int ct = tid & 15;   // col group: 8 cols
    int rt = tid >> 4;   // row group: 4 rows
    int c0 = ct * 8;
    int r0 = rt * 4;

    float acc[4][8];
    #pragma unroll
    for (int i = 0; i < 4; i++)
        #pragma unroll
        for (int j = 0; j < 8; j++) acc[i][j] = 0.f;

    #pragma unroll 8
    for (int k = 0; k < D; k++) {
        float a0 = As[(r0 + 0) * D + k];
        float a1 = As[(r0 + 1) * D + k];
        float a2 = As[(r0 + 2) * D + k];
        float a3 = As[(r0 + 3) * D + k];
        float4 w0 = *(const float4*)&Ws[k * D + c0];
        float4 w1 = *(const float4*)&Ws[k * D + c0 + 4];
        float wv[8] = {w0.x, w0.y, w0.z, w0.w, w1.x, w1.y, w1.z, w1.w};
        #pragma unroll
        for (int j = 0; j < 8; j++) {
            acc[0][j] = fmaf(a0, wv[j], acc[0][j]);
            acc[1][j] = fmaf(a1, wv[j], acc[1][j]);
            acc[2][j] = fmaf(a2, wv[j], acc[2][j]);
            acc[3][j] = fmaf(a3, wv[j], acc[3][j]);
        }
    }

    #pragma unroll
    for (int i = 0; i < 4; i++) {
        int row = row0 + r0 + i;
        if (row < n) {
            float4* dst = (float4*)&g_h[(size_t)row * D + c0];
            dst[0] = make_float4(acc[i][0], acc[i][1], acc[i][2], acc[i][3]);
            dst[1] = make_float4(acc[i][4], acc[i][5], acc[i][6], acc[i][7]);
        }
    }
}

// ---------------------------------------------------------------------------
// agg[i] = h[i] * dis[i]^2 + b   (self-loop contribution + bias)
__global__ void init_agg_kernel(const float* __restrict__ b,
                                float* __restrict__ out_ptr, int use_out) {
    int idx = blockIdx.x * blockDim.x + threadIdx.x;  // over NN*32 float4
    if (idx >= NN * 32) return;
    float* dst = use_out ? out_ptr : g_agg;
    int i  = idx >> 5;
    int c4 = idx & 31;
    float d  = g_dis[i];
    float d2 = d * d;
    float4 h = ((const float4*)g_h)[idx];
    float4 bb = ((const float4*)b)[c4];
    float4 o;
    o.x = fmaf(h.x, d2, bb.x);
    o.y = fmaf(h.y, d2, bb.y);
    o.z = fmaf(h.z, d2, bb.z);
    o.w = fmaf(h.w, d2, bb.w);
    ((float4*)dst)[idx] = o;
}

// ---------------------------------------------------------------------------
// One warp per edge: lanes cover the 128-float feature as 32 float4 chunks.
__global__ void scatter_kernel(const void* __restrict__ ei,
                               float* __restrict__ out_ptr, int use_out) {
    unsigned gid = blockIdx.x * blockDim.x + threadIdx.x;
    unsigned e = gid >> 5;
    if (e >= NE) return;
    int chunk = gid & 31;
    float* dst_base = use_out ? out_ptr : g_agg;

    int row = edge_at(ei, e);
    int col = edge_at(ei, NE + e);
    float norm = g_dis[row] * g_dis[col];

    float4 v = ((const float4*)g_h)[(size_t)row * 32 + chunk];
    float* dst = &dst_base[(size_t)col * D + chunk * 4];
    atomicAdd(dst + 0, v.x * norm);
    atomicAdd(dst + 1, v.y * norm);
    atomicAdd(dst + 2, v.z * norm);
    atomicAdd(dst + 3, v.w * norm);
}

// ---------------------------------------------------------------------------
__global__ void relu_kernel(float* __restrict__ p) {
    int idx = blockIdx.x * blockDim.x + threadIdx.x;  // over NN*32 float4
    if (idx >= NN * 32) return;
    float4 v = ((float4*)p)[idx];
    v.x = fmaxf(v.x, 0.f); v.y = fmaxf(v.y, 0.f);
    v.z = fmaxf(v.z, 0.f); v.w = fmaxf(v.w, 0.f);
    ((float4*)p)[idx] = v;
}

// ---------------------------------------------------------------------------
extern "C" void kernel_launch(void* const* d_in, const int* in_sizes, int n_in,
                              void* d_out, int out_size) {
    const float* x  = (const float*)d_in[0];
    const void*  ei = d_in[1];
    const float* W[3] = {(const float*)d_in[2], (const float*)d_in[4],
                         (const float*)d_in[6]};
    const float* b[3] = {(const float*)d_in[3], (const float*)d_in[5],
                         (const float*)d_in[7]};
    float* out = (float*)d_out;

    static bool attr_set = false;
    if (!attr_set) {
        cudaFuncSetAttribute(gemm_kernel,
                             cudaFuncAttributeMaxDynamicSharedMemorySize,
                             (TILE_M * D + D * D) * (int)sizeof(float));
        attr_set = true;
    }

    const int nodeVecBlocks = (NN * 32 + 255) / 256;     // 6250
    const int gemmBlocks    = (NN + TILE_M - 1) / TILE_M; // 782
    const int scatBlocks    = (NE * 32 + 255) / 256;     // 80000
    const size_t smem = (TILE_M * D + D * D) * sizeof(float); // 96 KB

    detect_idx_kernel<<<1, 1>>>(ei);
    deg_init_kernel<<<(NN + 255) / 256, 256>>>();
    deg_count_kernel<<<(NE + 255) / 256, 256>>>(ei);
    dis_fin_kernel<<<(NN + 255) / 256, 256>>>();

    for (int l = 0; l < 3; l++) {
        int relu_in    = (l > 0) ? 1 : 0;
        int src_is_agg = (l > 0) ? 1 : 0;
        int use_out    = (l == 2) ? 1 : 0;
        gemm_kernel<<<gemmBlocks, 256, smem>>>(x, W[l], NN, relu_in, src_is_agg);
        init_agg_kernel<<<nodeVecBlocks, 256>>>(b[l], out, use_out);
        scatter_kernel<<<scatBlocks, 256>>>(ei, out, use_out);
    }
    relu_kernel<<<nodeVecBlocks, 256>>>(out);
}

// round 2
// speedup vs baseline: 1.9752x; 1.9752x over previous
#include <cuda_runtime.h>
#include <stdint.h>

#define NN 50000
#define NE 640000
#define D  128
#define TILE_M 64

// Scratch (no allocations allowed)
__device__ float g_h[NN * D];      // post-GEMM features
__device__ float g_agg[NN * D];    // aggregated features (layers 1,2)
__device__ int   g_degi[NN];       // in-degree (edges only)
__device__ float g_dis[NN];        // rsqrt(deg+1)
__device__ int   g_off[NN + 1];    // CSR offsets (by col)
__device__ int   g_cur[NN];        // fill cursors
__device__ int   g_rows[NE];       // CSR: source row per incoming edge
__device__ float g_norm[NE];       // CSR: dis[row]*dis[col] per incoming edge
__device__ int   g_is64;

// ---------------------------------------------------------------------------
// Detect whether edge_index is int64 or int32 (values uniform in [0,50000)).
__global__ void detect_idx_kernel(const void* ei) {
    const long long* p = (const long long*)ei;
    int ok = 1;
    #pragma unroll
    for (int i = 0; i < 8; i++) {
        long long v = p[i];
        if (v < 0 || v >= NN) ok = 0;
    }
    g_is64 = ok;
}

__device__ __forceinline__ int edge_at(const void* ei, int pos) {
    if (g_is64) return (int)((const long long*)ei)[pos];
    return ((const int*)ei)[pos];
}

// ---------------------------------------------------------------------------
__global__ void zero_deg_kernel() {
    int i = blockIdx.x * blockDim.x + threadIdx.x;
    if (i < NN) g_degi[i] = 0;
}

__global__ void deg_count_kernel(const void* ei) {
    int e = blockIdx.x * blockDim.x + threadIdx.x;
    if (e >= NE) return;
    atomicAdd(&g_degi[edge_at(ei, NE + e)], 1);
}

__global__ void dis_kernel() {
    int i = blockIdx.x * blockDim.x + threadIdx.x;
    if (i < NN) g_dis[i] = rsqrtf((float)(g_degi[i] + 1));
}

// Single-block exclusive scan over g_degi -> g_off, copy to g_cur.
__global__ void scan_kernel() {
    __shared__ int ssum[1024];
    const int CH = (NN + 1023) / 1024;  // 49
    int t = threadIdx.x;
    int start = t * CH;
    int s = 0;
    for (int i = 0; i < CH; i++) {
        int idx = start + i;
        if (idx < NN) s += g_degi[idx];
    }
    ssum[t] = s;
    __syncthreads();
    for (int off = 1; off < 1024; off <<= 1) {
        int v = (t >= off) ? ssum[t - off] : 0;
        __syncthreads();
        ssum[t] += v;
        __syncthreads();
    }
    int run = (t == 0) ? 0 : ssum[t - 1];
    for (int i = 0; i < CH; i++) {
        int idx = start + i;
        if (idx < NN) {
            g_off[idx] = run;
            g_cur[idx] = run;
            run += g_degi[idx];
        }
    }
    if (t == 0) g_off[NN] = ssum[1023];
}

__global__ void fill_kernel(const void* ei) {
    int e = blockIdx.x * blockDim.x + threadIdx.x;
    if (e >= NE) return;
    int row = edge_at(ei, e);
    int col = edge_at(ei, NE + e);
    int pos = atomicAdd(&g_cur[col], 1);
    g_rows[pos] = row;
    g_norm[pos] = g_dis[row] * g_dis[col];
}

// ---------------------------------------------------------------------------
// C[n x 128] = A[n x 128] @ W[128 x 128], optional ReLU on A read.
__global__ void gemm_kernel(const float* __restrict__ Ain,
                            const float* __restrict__ W,
                            int n, int relu_in, int src_is_agg) {
    extern __shared__ float sm[];
    float* As = sm;               // 64 * 128
    float* Ws = sm + TILE_M * D;  // 128 * 128

    const float* A = src_is_agg ? g_agg : Ain;
    int tid  = threadIdx.x;
    int row0 = blockIdx.x * TILE_M;

    const float4* W4  = (const float4*)W;
    float4*       Ws4 = (float4*)Ws;
    #pragma unroll
    for (int i = 0; i < 16; i++) Ws4[tid + i * 256] = W4[tid + i * 256];

    const float4* A4  = (const float4*)A;
    float4*       As4 = (float4*)As;
    #pragma unroll
    for (int i = 0; i < 8; i++) {
        int idx = tid + i * 256;
        int r   = idx >> 5;
        int c4  = idx & 31;
        float4 v = make_float4(0.f, 0.f, 0.f, 0.f);
        if (row0 + r < n) {
            v = A4[(size_t)(row0 + r) * 32 + c4];
            if (relu_in) {
                v.x = fmaxf(v.x, 0.f); v.y = fmaxf(v.y, 0.f);
                v.z = fmaxf(v.z, 0.f); v.w = fmaxf(v.w, 0.f);
            }
        }
        As4[idx] = v;
    }
    __syncthreads();

    int ct = tid & 15;
    int rt = tid >> 4;
    int c0 = ct * 8;
    int r0 = rt * 4;

    float acc[4][8];
    #pragma unroll
    for (int i = 0; i < 4; i++)
        #pragma unroll
        for (int j = 0; j < 8; j++) acc[i][j] = 0.f;

    #pragma unroll 8
    for (int k = 0; k < D; k++) {
        float a0 = As[(r0 + 0) * D + k];
        float a1 = As[(r0 + 1) * D + k];
        float a2 = As[(r0 + 2) * D + k];
        float a3 = As[(r0 + 3) * D + k];
        float4 w0 = *(const float4*)&Ws[k * D + c0];
        float4 w1 = *(const float4*)&Ws[k * D + c0 + 4];
        float wv[8] = {w0.x, w0.y, w0.z, w0.w, w1.x, w1.y, w1.z, w1.w};
        #pragma unroll
        for (int j = 0; j < 8; j++) {
            acc[0][j] = fmaf(a0, wv[j], acc[0][j]);
            acc[1][j] = fmaf(a1, wv[j], acc[1][j]);
            acc[2][j] = fmaf(a2, wv[j], acc[2][j]);
            acc[3][j] = fmaf(a3, wv[j], acc[3][j]);
        }
    }

    #pragma unroll
    for (int i = 0; i < 4; i++) {
        int row = row0 + r0 + i;
        if (row < n) {
            float4* dst = (float4*)&g_h[(size_t)row * D + c0];
            dst[0] = make_float4(acc[i][0], acc[i][1], acc[i][2], acc[i][3]);
            dst[1] = make_float4(acc[i][4], acc[i][5], acc[i][6], acc[i][7]);
        }
    }
}

// ---------------------------------------------------------------------------
// Gather-based aggregation: one warp per node.
// acc = b + h[node]*dis[node]^2 + sum_{incoming j} h[rows[j]] * norm[j]
// Optional ReLU on write (final layer).
__global__ void gather_kernel(const float* __restrict__ b,
                              float* __restrict__ out_ptr,
                              int use_out, int relu_out) {
    unsigned gid = blockIdx.x * blockDim.x + threadIdx.x;
    unsigned node = gid >> 5;
    if (node >= NN) return;
    int lane = threadIdx.x & 31;
    float* dst = use_out ? out_ptr : g_agg;

    const float4* h4 = (const float4*)g_h;

    float di = g_dis[node];
    float d2 = di * di;
    float4 bb = ((const float4*)b)[lane];
    float4 hs = h4[(size_t)node * 32 + lane];
    float4 acc;
    acc.x = fmaf(hs.x, d2, bb.x);
    acc.y = fmaf(hs.y, d2, bb.y);
    acc.z = fmaf(hs.z, d2, bb.z);
    acc.w = fmaf(hs.w, d2, bb.w);

    int s = g_off[node];
    int e = g_off[node + 1];
    int j = s;
    for (; j + 3 < e; j += 4) {
        int   r0 = g_rows[j],     r1 = g_rows[j + 1];
        int   r2 = g_rows[j + 2], r3 = g_rows[j + 3];
        float n0 = g_norm[j],     n1 = g_norm[j + 1];
        float n2 = g_norm[j + 2], n3 = g_norm[j + 3];
        float4 v0 = h4[(size_t)r0 * 32 + lane];
        float4 v1 = h4[(size_t)r1 * 32 + lane];
        float4 v2 = h4[(size_t)r2 * 32 + lane];
        float4 v3 = h4[(size_t)r3 * 32 + lane];
        acc.x = fmaf(v0.x, n0, acc.x); acc.y = fmaf(v0.y, n0, acc.y);
        acc.z = fmaf(v0.z, n0, acc.z); acc.w = fmaf(v0.w, n0, acc.w);
        acc.x = fmaf(v1.x, n1, acc.x); acc.y = fmaf(v1.y, n1, acc.y);
        acc.z = fmaf(v1.z, n1, acc.z); acc.w = fmaf(v1.w, n1, acc.w);
        acc.x = fmaf(v2.x, n2, acc.x); acc.y = fmaf(v2.y, n2, acc.y);
        acc.z = fmaf(v2.z, n2, acc.z); acc.w = fmaf(v2.w, n2, acc.w);
        acc.x = fmaf(v3.x, n3, acc.x); acc.y = fmaf(v3.y, n3, acc.y);
        acc.z = fmaf(v3.z, n3, acc.z); acc.w = fmaf(v3.w, n3, acc.w);
    }
    for (; j < e; j++) {
        int   r = g_rows[j];
        float nm = g_norm[j];
        float4 v = h4[(size_t)r * 32 + lane];
        acc.x = fmaf(v.x, nm, acc.x); acc.y = fmaf(v.y, nm, acc.y);
        acc.z = fmaf(v.z, nm, acc.z); acc.w = fmaf(v.w, nm, acc.w);
    }

    if (relu_out) {
        acc.x = fmaxf(acc.x, 0.f); acc.y = fmaxf(acc.y, 0.f);
        acc.z = fmaxf(acc.z, 0.f); acc.w = fmaxf(acc.w, 0.f);
    }
    ((float4*)dst)[(size_t)node * 32 + lane] = acc;
}

// ---------------------------------------------------------------------------
extern "C" void kernel_launch(void* const* d_in, const int* in_sizes, int n_in,
                              void* d_out, int out_size) {
    const float* x  = (const float*)d_in[0];
    const void*  ei = d_in[1];
    const float* W[3] = {(const float*)d_in[2], (const float*)d_in[4],
                         (const float*)d_in[6]};
    const float* b[3] = {(const float*)d_in[3], (const float*)d_in[5],
                         (const float*)d_in[7]};
    float* out = (float*)d_out;

    static bool attr_set = false;
    if (!attr_set) {
        cudaFuncSetAttribute(gemm_kernel,
                             cudaFuncAttributeMaxDynamicSharedMemorySize,
                             (TILE_M * D + D * D) * (int)sizeof(float));
        attr_set = true;
    }

    const int nodeBlocks  = (NN + 255) / 256;             // 196
    const int edgeBlocks  = (NE + 255) / 256;             // 2500
    const int gemmBlocks  = (NN + TILE_M - 1) / TILE_M;   // 782
    const int gatherBlocks = (NN * 32 + 255) / 256;       // 6250 (warp/node)
    const size_t smem = (TILE_M * D + D * D) * sizeof(float);

    detect_idx_kernel<<<1, 1>>>(ei);
    zero_deg_kernel<<<nodeBlocks, 256>>>();
    deg_count_kernel<<<edgeBlocks, 256>>>(ei);
    dis_kernel<<<nodeBlocks, 256>>>();
    scan_kernel<<<1, 1024>>>();
    fill_kernel<<<edgeBlocks, 256>>>(ei);

    for (int l = 0; l < 3; l++) {
        int relu_in    = (l > 0) ? 1 : 0;
        int src_is_agg = (l > 0) ? 1 : 0;
        int use_out    = (l == 2) ? 1 : 0;
        int relu_out   = (l == 2) ? 1 : 0;
        gemm_kernel<<<gemmBlocks, 256, smem>>>(x, W[l], NN, relu_in, src_is_agg);
        gather_kernel<<<gatherBlocks, 256>>>(b[l], out, use_out, relu_out);
    }
}